// round 1
// baseline (speedup 1.0000x reference)
#include <cuda_runtime.h>
#include <math.h>

#define H 128
#define G 50
#define NBINS 8192
#define CUTOFF_F 10.0f
#define NMAX 10000
#define PI_F 3.14159265358979323846f

__device__ __align__(16) float g_h[NMAX * H];
__device__ __align__(16) float g_xf[NMAX * H];
__device__ __align__(16) float g_agg[NMAX * H];
__device__ __align__(16) float g_tmp[NMAX * H];
__device__ __align__(16) float g_tt[(NBINS + 1) * H];
__device__ __align__(16) float g_table[(NBINS + 1) * H];
__device__ float g_acc[64];

__device__ __forceinline__ float sspf(float x) {
    // softplus(x) - log(2), numerically stable
    return fmaxf(x, 0.f) + log1pf(expf(-fabsf(x))) - 0.69314718055994530942f;
}

// h[n] = emb[x[n]]
__global__ void embed_kernel(const int* __restrict__ x, const float* __restrict__ emb, int N) {
    int n = blockIdx.x;
    if (n < N) g_h[n * H + threadIdx.x] = emb[x[n] * H + threadIdx.x];
}

__global__ void zero_kernel(float* p, int n) {
    for (int i = blockIdx.x * blockDim.x + threadIdx.x; i < n; i += gridDim.x * blockDim.x)
        p[i] = 0.f;
}

// Stage 1 of table build: g_tt[b][f] = ssp( sum_g ea(d_b)[g] * w1[g][f] + b1[f] )
__global__ void table_stage1(const float* __restrict__ w1, const float* __restrict__ b1) {
    __shared__ float w1s[G * H];
    __shared__ float eas[G];
    __shared__ float b1s[H];
    int t = threadIdx.x;  // 128 threads
    for (int i = t; i < G * H; i += H) w1s[i] = w1[i];
    b1s[t] = b1[t];
    __syncthreads();
    const float spacing = CUTOFF_F / (G - 1);
    const float coeff = -0.5f / (spacing * spacing);
    for (int b = blockIdx.x; b <= NBINS; b += gridDim.x) {
        float d = b * (CUTOFF_F / NBINS);
        if (t < G) {
            float dd = d - t * spacing;
            eas[t] = expf(coeff * dd * dd);
        }
        __syncthreads();
        float a = b1s[t];
#pragma unroll
        for (int g = 0; g < G; g++) a += eas[g] * w1s[g * H + t];
        g_tt[b * H + t] = sspf(a);
        __syncthreads();
    }
}

// Generic C[M,128] = epilogue(A[M,128] @ W[128,128] + bias)
#define GF_BIAS 1
#define GF_SSP  2
#define GF_CUT  4
#define GF_ACC  8
__global__ void gemm128(const float* __restrict__ A, const float* __restrict__ W,
                        const float* __restrict__ bias, float* __restrict__ out,
                        int M, int flags) {
    __shared__ float Ws[32][128];
    __shared__ float As[32][33];
    int f = threadIdx.x;  // 128 threads, one output column each
    int r0 = blockIdx.x * 32;
    float bv = (flags & GF_BIAS) ? bias[f] : 0.f;
    float acc[32];
#pragma unroll
    for (int r = 0; r < 32; r++) acc[r] = 0.f;
    for (int k0 = 0; k0 < 128; k0 += 32) {
        // W tile: thread f loads Ws[kk][f] for kk=0..31 (coalesced)
        for (int i = f; i < 32 * 128; i += 128) {
            int kk = i >> 7, ff = i & 127;
            Ws[kk][ff] = W[(k0 + kk) * 128 + ff];
        }
        // A tile: 32 rows x 32 cols
        for (int i = f; i < 32 * 32; i += 128) {
            int r = i >> 5, kk = i & 31;
            int row = r0 + r;
            As[r][kk] = (row < M) ? A[row * 128 + k0 + kk] : 0.f;
        }
        __syncthreads();
#pragma unroll 8
        for (int kk = 0; kk < 32; kk++) {
            float w = Ws[kk][f];
#pragma unroll
            for (int r = 0; r < 32; r++) acc[r] += As[r][kk] * w;
        }
        __syncthreads();
    }
#pragma unroll 4
    for (int r = 0; r < 32; r++) {
        int row = r0 + r;
        if (row >= M) break;
        float v = acc[r] + bv;
        if (flags & GF_SSP) v = sspf(v);
        if (flags & GF_CUT) {
            float d = row * (CUTOFF_F / NBINS);
            v *= 0.5f * (cosf(d * (PI_F / CUTOFF_F)) + 1.f);
        }
        if (flags & GF_ACC) out[row * 128 + f] += v;
        else out[row * 128 + f] = v;
    }
}

// Fused edge pass: W=lerp(table, d); agg[dst] += xf[src] * W   (one warp per edge)
__global__ void edge_kernel(const float* __restrict__ dist, const int* __restrict__ ei, int E) {
    int tid = blockIdx.x * blockDim.x + threadIdx.x;
    int lane = tid & 31;
    int warp = tid >> 5;
    int nw = (gridDim.x * blockDim.x) >> 5;
    const int* src = ei;
    const int* dst = ei + E;
    for (int e = warp; e < E; e += nw) {
        float d = dist[e];
        float u = d * ((float)NBINS / CUTOFF_F);
        int i0 = (int)u;
        i0 = min(max(i0, 0), NBINS - 1);
        float fr = u - (float)i0;
        const float4* t0 = (const float4*)(g_table + (size_t)i0 * H) + lane;
        float4 w0 = t0[0];
        float4 w1 = t0[32];  // next bin row (128 floats = 32 float4s ahead)
        float4 xv = ((const float4*)(g_xf + (size_t)src[e] * H))[lane];
        float4 m;
        m.x = xv.x * fmaf(fr, w1.x - w0.x, w0.x);
        m.y = xv.y * fmaf(fr, w1.y - w0.y, w0.y);
        m.z = xv.z * fmaf(fr, w1.z - w0.z, w0.z);
        m.w = xv.w * fmaf(fr, w1.w - w0.w, w0.w);
        float* ap = g_agg + (size_t)dst[e] * H + lane * 4;
        asm volatile("red.global.add.v4.f32 [%0], {%1,%2,%3,%4};"
                     :: "l"(ap), "f"(m.x), "f"(m.y), "f"(m.z), "f"(m.w)
                     : "memory");
    }
}

// Readout stage 1: t = ssp(h@out1_w+b1); t2 = t@out2_w+b2; g_acc += sum_rows(t2)
__global__ void readout1(const float* __restrict__ o1w, const float* __restrict__ o1b,
                         const float* __restrict__ o2w, const float* __restrict__ o2b, int N) {
    __shared__ float ts[64][65];
    int f = threadIdx.x;  // 64 threads
    int r0 = blockIdx.x * 64;
    float psum = 0.f;
    for (int r = 0; r < 64; r++) {
        int row = r0 + r;
        if (row >= N) break;
        float a = o1b[f];
        const float* hr = g_h + (size_t)row * H;
#pragma unroll 8
        for (int j = 0; j < H; j++) a += hr[j] * o1w[j * 64 + f];
        ts[r][f] = sspf(a);
    }
    __syncthreads();
    for (int r = 0; r < 64; r++) {
        int row = r0 + r;
        if (row >= N) break;
        float a = o2b[f];
#pragma unroll 8
        for (int j = 0; j < 64; j++) a += ts[r][j] * o2w[j * 64 + f];
        psum += a;
    }
    atomicAdd(&g_acc[f], psum);
}

// Readout stage 2: out = g_acc @ ro_w + ro_b  -> [12]
__global__ void readout2(const float* __restrict__ rw, const float* __restrict__ rb,
                         float* __restrict__ out) {
    int k = threadIdx.x;
    if (k < 12) {
        float a = rb[k];
#pragma unroll
        for (int j = 0; j < 64; j++) a += g_acc[j] * rw[j * 12 + k];
        out[k] = a;
    }
}

extern "C" void kernel_launch(void* const* d_in, const int* in_sizes, int n_in,
                              void* d_out, int out_size) {
    const int*   x    = (const int*)d_in[0];
    const int*   ei   = (const int*)d_in[1];
    const float* dist = (const float*)d_in[2];
    const float* emb  = (const float*)d_in[3];
    const float* mw1  = (const float*)d_in[4];
    const float* mb1  = (const float*)d_in[5];
    const float* mw2  = (const float*)d_in[6];
    const float* mb2  = (const float*)d_in[7];
    const float* l1w  = (const float*)d_in[8];
    const float* l2w  = (const float*)d_in[9];
    const float* l2b  = (const float*)d_in[10];
    const float* lw   = (const float*)d_in[11];
    const float* lb   = (const float*)d_in[12];
    const float* o1w  = (const float*)d_in[13];
    const float* o1b  = (const float*)d_in[14];
    const float* o2w  = (const float*)d_in[15];
    const float* o2b  = (const float*)d_in[16];
    const float* rw   = (const float*)d_in[17];
    const float* rb   = (const float*)d_in[18];

    int N = in_sizes[0];
    int E = in_sizes[2];
    int L = in_sizes[4] / (G * H);

    float *ph, *pxf, *pagg, *ptmp, *ptt, *ptab, *pacc;
    cudaGetSymbolAddress((void**)&ph, g_h);
    cudaGetSymbolAddress((void**)&pxf, g_xf);
    cudaGetSymbolAddress((void**)&pagg, g_agg);
    cudaGetSymbolAddress((void**)&ptmp, g_tmp);
    cudaGetSymbolAddress((void**)&ptt, g_tt);
    cudaGetSymbolAddress((void**)&ptab, g_table);
    cudaGetSymbolAddress((void**)&pacc, g_acc);

    embed_kernel<<<N, 128>>>(x, emb, N);
    zero_kernel<<<1, 64>>>(pacc, 64);

    int nbN = (N + 31) / 32;
    int nbT = (NBINS + 1 + 31) / 32;

    for (int l = 0; l < L; l++) {
        // Build per-layer filter table W(d)*C(d) over 8193 distance bins
        table_stage1<<<256, 128>>>(mw1 + (size_t)l * G * H, mb1 + (size_t)l * H);
        gemm128<<<nbT, 128>>>(ptt, mw2 + (size_t)l * H * H, mb2 + (size_t)l * H,
                              ptab, NBINS + 1, GF_BIAS | GF_CUT);
        // xf = h @ lin1_w (no bias)
        gemm128<<<nbN, 128>>>(ph, l1w + (size_t)l * H * H, nullptr, pxf, N, 0);
        // message pass
        zero_kernel<<<256, 256>>>(pagg, N * H);
        edge_kernel<<<2048, 256>>>(dist, ei, E);
        // tmp = ssp(agg @ lin2_w + lin2_b)
        gemm128<<<nbN, 128>>>(pagg, l2w + (size_t)l * H * H, l2b + (size_t)l * H,
                              ptmp, N, GF_BIAS | GF_SSP);
        // h += tmp @ lin_w + lin_b
        gemm128<<<nbN, 128>>>(ptmp, lw + (size_t)l * H * H, lb + (size_t)l * H,
                              ph, N, GF_BIAS | GF_ACC);
    }

    readout1<<<(N + 63) / 64, 64>>>(o1w, o1b, o2w, o2b, N);
    readout2<<<1, 32>>>(rw, rb, (float*)d_out);
}

// round 2
// speedup vs baseline: 2.0905x; 2.0905x over previous
#include <cuda_runtime.h>
#include <cuda_fp16.h>
#include <math.h>

#define H 128
#define G 50
#define NBINS 1024
#define CUTOFF_F 10.0f
#define NMAX 10000
#define PI_F 3.14159265358979323846f

__device__ __align__(16) float  g_h[NMAX * H];
__device__ __align__(16) __half g_xfh[NMAX * H];
__device__ __align__(16) float  g_agg[NMAX * H];
__device__ __align__(16) float  g_tmp[NMAX * H];
__device__ __align__(16) float  g_tt[(NBINS + 1) * H];
__device__ __align__(16) float  g_table[(NBINS + 1) * H];
__device__ __align__(16) __half2 g_tableh[NBINS * H];   // [bin][f] = (W[bin][f], W[bin+1][f])
__device__ float g_acc[64];

__device__ __forceinline__ float sspf(float x) {
    return fmaxf(x, 0.f) + log1pf(expf(-fabsf(x))) - 0.69314718055994530942f;
}

// ---- f32x2 packed-FMA helpers (FFMA-3reg is half rate on sm_103a; f32x2 is full rate) ----
__device__ __forceinline__ void fma2(unsigned long long& d, unsigned long long a, unsigned long long b) {
    asm("fma.rn.f32x2 %0, %1, %2, %0;" : "+l"(d) : "l"(a), "l"(b));
}
__device__ __forceinline__ unsigned long long bcast2(float a) {
    unsigned long long r; asm("mov.b64 %0, {%1, %1};" : "=l"(r) : "f"(a)); return r;
}
__device__ __forceinline__ float2 unpack2(unsigned long long v) {
    float2 f; asm("mov.b64 {%0, %1}, %2;" : "=f"(f.x), "=f"(f.y) : "l"(v)); return f;
}

// h[n] = emb[x[n]]
__global__ void embed_kernel(const int* __restrict__ x, const float* __restrict__ emb, int N) {
    int n = blockIdx.x;
    if (n < N) g_h[n * H + threadIdx.x] = emb[x[n] * H + threadIdx.x];
}

// g_tt[b][f] = ssp( sum_g ea(d_b)[g] * w1[g][f] + b1[f] )
__global__ void table_stage1(const float* __restrict__ w1, const float* __restrict__ b1) {
    __shared__ float w1s[G * H];
    __shared__ float eas[G];
    __shared__ float b1s[H];
    int t = threadIdx.x;  // 128
    for (int i = t; i < G * H; i += H) w1s[i] = w1[i];
    b1s[t] = b1[t];
    __syncthreads();
    const float spacing = CUTOFF_F / (G - 1);
    const float coeff = -0.5f / (spacing * spacing);
    for (int b = blockIdx.x; b <= NBINS; b += gridDim.x) {
        float d = b * (CUTOFF_F / NBINS);
        if (t < G) {
            float dd = d - t * spacing;
            eas[t] = expf(coeff * dd * dd);
        }
        __syncthreads();
        float a = b1s[t];
#pragma unroll
        for (int g = 0; g < G; g++) a += eas[g] * w1s[g * H + t];
        g_tt[b * H + t] = sspf(a);
        __syncthreads();
    }
}

// Pack fp32 table -> half2 (both lerp endpoints in one 32-bit word)
__global__ void pack_table() {
    int idx = blockIdx.x * blockDim.x + threadIdx.x;
    if (idx < NBINS * H)
        g_tableh[idx] = __floats2half2_rn(g_table[idx], g_table[idx + H]);
}

// ---- Generic tiled GEMM: C[M,NCOL] = epi(A[M,128] @ W[128,NCOL] + bias) ----
#define GF_BIAS   1
#define GF_SSP    2
#define GF_CUT    4
#define GF_ACC    8
#define GF_HALF   16
#define GF_COLSUM 32

template<int NCOL, int FLAGS>
__global__ void __launch_bounds__(256) gemm_t(
    const float* __restrict__ A, const float* __restrict__ W,
    const float* __restrict__ bias, float* __restrict__ out, int M)
{
    constexpr int CT = NCOL / 4;   // threads across columns
    constexpr int RT = 256 / CT;   // threads across rows
    constexpr int ROWS = RT * 4;   // rows per block
    __shared__ float As[ROWS][33];
    __shared__ float Ws[32][NCOL];
    __shared__ float csum[NCOL];
    int tid = threadIdx.x;
    int tx = tid % CT, ty = tid / CT;
    int r0 = blockIdx.x * ROWS;
    if ((FLAGS & GF_COLSUM) && tid < NCOL) csum[tid] = 0.f;
    unsigned long long a01[4] = {0ull, 0ull, 0ull, 0ull};
    unsigned long long a23[4] = {0ull, 0ull, 0ull, 0ull};

    for (int k0 = 0; k0 < 128; k0 += 32) {
        __syncthreads();
        for (int i = tid; i < ROWS * 32; i += 256) {
            int r = i >> 5, kk = i & 31;
            int row = r0 + r;
            As[r][kk] = (row < M) ? A[(size_t)row * 128 + k0 + kk] : 0.f;
        }
        for (int i = tid; i < 32 * NCOL; i += 256) {
            int kk = i / NCOL, c = i % NCOL;
            Ws[kk][c] = W[(size_t)(k0 + kk) * NCOL + c];
        }
        __syncthreads();
#pragma unroll
        for (int kk = 0; kk < 32; kk++) {
            ulonglong2 wv = *(const ulonglong2*)&Ws[kk][tx * 4];
#pragma unroll
            for (int i = 0; i < 4; i++) {
                unsigned long long a2 = bcast2(As[ty * 4 + i][kk]);
                fma2(a01[i], a2, wv.x);
                fma2(a23[i], a2, wv.y);
            }
        }
    }

    float4 bv = make_float4(0.f, 0.f, 0.f, 0.f);
    if (FLAGS & GF_BIAS) bv = *(const float4*)&bias[tx * 4];
#pragma unroll
    for (int i = 0; i < 4; i++) {
        int row = r0 + ty * 4 + i;
        if (row >= M) break;
        float2 p0 = unpack2(a01[i]);
        float2 p1 = unpack2(a23[i]);
        float v0 = p0.x + bv.x, v1 = p0.y + bv.y, v2 = p1.x + bv.z, v3 = p1.y + bv.w;
        if (FLAGS & GF_SSP) { v0 = sspf(v0); v1 = sspf(v1); v2 = sspf(v2); v3 = sspf(v3); }
        if (FLAGS & GF_CUT) {
            float d = row * (CUTOFF_F / NBINS);
            float c = 0.5f * (cosf(d * (PI_F / CUTOFF_F)) + 1.f);
            v0 *= c; v1 *= c; v2 *= c; v3 *= c;
        }
        if (FLAGS & GF_COLSUM) {
            atomicAdd(&csum[tx * 4 + 0], v0);
            atomicAdd(&csum[tx * 4 + 1], v1);
            atomicAdd(&csum[tx * 4 + 2], v2);
            atomicAdd(&csum[tx * 4 + 3], v3);
        } else if (FLAGS & GF_HALF) {
            __half2* op = (__half2*)out;
            size_t base = ((size_t)row * NCOL + tx * 4) >> 1;
            op[base]     = __floats2half2_rn(v0, v1);
            op[base + 1] = __floats2half2_rn(v2, v3);
        } else if (FLAGS & GF_ACC) {
            float4* op = (float4*)&out[(size_t)row * NCOL + tx * 4];
            float4 o = *op;
            o.x += v0; o.y += v1; o.z += v2; o.w += v3;
            *op = o;
        } else {
            *(float4*)&out[(size_t)row * NCOL + tx * 4] = make_float4(v0, v1, v2, v3);
        }
    }
    if (FLAGS & GF_COLSUM) {
        __syncthreads();
        if (tid < NCOL) atomicAdd(&g_acc[tid], csum[tid]);
    }
}

// Fused edge pass: W = lerp(half2 table, d); agg[dst] += xf[src]*W  (warp per edge)
__global__ void edge_kernel(const float* __restrict__ dist, const int* __restrict__ ei, int E) {
    int tid = blockIdx.x * blockDim.x + threadIdx.x;
    int lane = tid & 31;
    int warp = tid >> 5;
    int nw = (gridDim.x * blockDim.x) >> 5;
    const int* src = ei;
    const int* dst = ei + E;
    for (int e = warp; e < E; e += nw) {
        float d = dist[e];
        float u = d * ((float)NBINS / CUTOFF_F);
        int i0 = min(max((int)u, 0), NBINS - 1);
        float fr = u - (float)i0;
        float4 wq = ((const float4*)(g_tableh + (size_t)i0 * H))[lane];   // 4 half2 pairs
        uint2  xq = ((const uint2*)(g_xfh + (size_t)src[e] * H))[lane];   // 4 halves
        const __half2* wp = (const __half2*)&wq;
        const __half*  xp = (const __half*)&xq;
        float m[4];
#pragma unroll
        for (int j = 0; j < 4; j++) {
            float2 w2 = __half22float2(wp[j]);
            float w = fmaf(fr, w2.y - w2.x, w2.x);
            m[j] = __half2float(xp[j]) * w;
        }
        float* ap = g_agg + (size_t)dst[e] * H + lane * 4;
        asm volatile("red.global.add.v4.f32 [%0], {%1,%2,%3,%4};"
                     :: "l"(ap), "f"(m[0]), "f"(m[1]), "f"(m[2]), "f"(m[3])
                     : "memory");
    }
}

// out = (g_acc @ o2w + N*o2b) @ ro_w + ro_b
__global__ void readout_final(const float* __restrict__ o2w, const float* __restrict__ o2b,
                              const float* __restrict__ rw, const float* __restrict__ rb,
                              float* __restrict__ out, int N) {
    __shared__ float v[64];
    int t = threadIdx.x;  // 64
    float a = (float)N * o2b[t];
#pragma unroll 8
    for (int j = 0; j < 64; j++) a += g_acc[j] * o2w[j * 64 + t];
    v[t] = a;
    __syncthreads();
    if (t < 12) {
        float r = rb[t];
#pragma unroll
        for (int j = 0; j < 64; j++) r += v[j] * rw[j * 12 + t];
        out[t] = r;
    }
}

extern "C" void kernel_launch(void* const* d_in, const int* in_sizes, int n_in,
                              void* d_out, int out_size) {
    const int*   x    = (const int*)d_in[0];
    const int*   ei   = (const int*)d_in[1];
    const float* dist = (const float*)d_in[2];
    const float* emb  = (const float*)d_in[3];
    const float* mw1  = (const float*)d_in[4];
    const float* mb1  = (const float*)d_in[5];
    const float* mw2  = (const float*)d_in[6];
    const float* mb2  = (const float*)d_in[7];
    const float* l1w  = (const float*)d_in[8];
    const float* l2w  = (const float*)d_in[9];
    const float* l2b  = (const float*)d_in[10];
    const float* lw   = (const float*)d_in[11];
    const float* lb   = (const float*)d_in[12];
    const float* o1w  = (const float*)d_in[13];
    const float* o1b  = (const float*)d_in[14];
    const float* o2w  = (const float*)d_in[15];
    const float* o2b  = (const float*)d_in[16];
    const float* rw   = (const float*)d_in[17];
    const float* rb   = (const float*)d_in[18];

    int N = in_sizes[0];
    int E = in_sizes[2];
    int L = in_sizes[4] / (G * H);

    float *ph, *pxfh, *pagg, *ptmp, *ptt, *ptab, *pacc;
    cudaGetSymbolAddress((void**)&ph, g_h);
    cudaGetSymbolAddress((void**)&pxfh, g_xfh);
    cudaGetSymbolAddress((void**)&pagg, g_agg);
    cudaGetSymbolAddress((void**)&ptmp, g_tmp);
    cudaGetSymbolAddress((void**)&ptt, g_tt);
    cudaGetSymbolAddress((void**)&ptab, g_table);
    cudaGetSymbolAddress((void**)&pacc, g_acc);

    embed_kernel<<<N, 128>>>(x, emb, N);

    int nbN  = (N + 31) / 32;                 // NCOL=128 gemm: 32 rows/block
    int nbT  = (NBINS + 1 + 31) / 32;
    int nbR  = (N + 63) / 64;                 // NCOL=64 gemm: 64 rows/block

    for (int l = 0; l < L; l++) {
        // xf(fp16) = h @ lin1_w   (independent of table build)
        gemm_t<128, GF_HALF><<<nbN, 256>>>(ph, l1w + (size_t)l * H * H, nullptr, (float*)pxfh, N);
        // per-layer filter table W(d)*C(d), then pack fp32 -> half2 lerp pairs
        table_stage1<<<128, 128>>>(mw1 + (size_t)l * G * H, mb1 + (size_t)l * H);
        gemm_t<128, GF_BIAS | GF_CUT><<<nbT, 256>>>(ptt, mw2 + (size_t)l * H * H,
                                                    mb2 + (size_t)l * H, ptab, NBINS + 1);
        pack_table<<<(NBINS * H + 255) / 256, 256>>>();
        // message pass
        cudaMemsetAsync(pagg, 0, (size_t)N * H * sizeof(float));
        edge_kernel<<<2048, 256>>>(dist, ei, E);
        // tmp = ssp(agg @ lin2_w + lin2_b);  h += tmp @ lin_w + lin_b
        gemm_t<128, GF_BIAS | GF_SSP><<<nbN, 256>>>(pagg, l2w + (size_t)l * H * H,
                                                    l2b + (size_t)l * H, ptmp, N);
        gemm_t<128, GF_BIAS | GF_ACC><<<nbN, 256>>>(ptmp, lw + (size_t)l * H * H,
                                                    lb + (size_t)l * H, ph, N);
    }

    // readout: colsum of ssp(h@o1w+o1b), then tiny final stage
    cudaMemsetAsync(pacc, 0, 64 * sizeof(float));
    gemm_t<64, GF_BIAS | GF_SSP | GF_COLSUM><<<nbR, 256>>>(ph, o1w, o1b, nullptr, N);
    readout_final<<<1, 64>>>(o2w, o2b, rw, rb, (float*)d_out, N);
}

// round 4
// speedup vs baseline: 2.4762x; 1.1845x over previous
#include <cuda_runtime.h>
#include <cuda_fp16.h>
#include <math.h>

#define H 128
#define G 50
#define NBINS 1024
#define CUTOFF_F 10.0f
#define NMAX 10000
#define EMAX 320000
#define PI_F 3.14159265358979323846f

__device__ __align__(16) float  g_h[NMAX * H];
__device__ __align__(16) __half g_xfh[NMAX * H];
__device__ __align__(16) float  g_agg[NMAX * H];
__device__ __align__(16) float  g_tmp[NMAX * H];
__device__ __align__(16) __half g_tabh[(NBINS + 2) * H];
__device__ float g_acc[64];
__device__ int  g_rowptr[NMAX + 1];
__device__ int  g_cursor[NMAX];
__device__ __align__(16) int2 g_csr[EMAX];

__device__ __forceinline__ float sspf(float x) {
    return fmaxf(x, 0.f) + log1pf(expf(-fabsf(x))) - 0.69314718055994530942f;
}

__device__ __forceinline__ unsigned int h2_as_u32(__half2 h) {
    return *reinterpret_cast<unsigned int*>(&h);
}

// ---- f32x2 packed-FMA helpers ----
__device__ __forceinline__ void fma2(unsigned long long& d, unsigned long long a, unsigned long long b) {
    asm("fma.rn.f32x2 %0, %1, %2, %0;" : "+l"(d) : "l"(a), "l"(b));
}
__device__ __forceinline__ unsigned long long bcast2(float a) {
    unsigned long long r; asm("mov.b64 %0, {%1, %1};" : "=l"(r) : "f"(a)); return r;
}
__device__ __forceinline__ unsigned long long pack2(float a, float b) {
    unsigned long long r; asm("mov.b64 %0, {%1, %2};" : "=l"(r) : "f"(a), "f"(b)); return r;
}
__device__ __forceinline__ float2 unpack2(unsigned long long v) {
    float2 f; asm("mov.b64 {%0, %1}, %2;" : "=f"(f.x), "=f"(f.y) : "l"(v)); return f;
}

// h[n] = emb[x[n]]
__global__ void embed_kernel(const int* __restrict__ x, const float* __restrict__ emb, int N) {
    int n = blockIdx.x;
    if (n < N) g_h[n * H + threadIdx.x] = emb[x[n] * H + threadIdx.x];
}

// ======================= CSR build =======================
__global__ void hist_kernel(const int* __restrict__ dst, int E) {
    int e = blockIdx.x * blockDim.x + threadIdx.x;
    if (e < E) atomicAdd(&g_rowptr[dst[e] + 1], 1);
}

__global__ void __launch_bounds__(1024) scan_kernel(int n) {
    __shared__ int sums[1024];
    int t = threadIdx.x;
    int C = (n + 1023) / 1024;   // <= 12 for NMAX 10000
    int local[12];
    int base = t * C;
    int s = 0;
#pragma unroll
    for (int i = 0; i < 12; i++) {
        if (i >= C) break;
        int idx = base + i;
        int v = (idx < n) ? g_rowptr[idx] : 0;
        s += v; local[i] = s;
    }
    sums[t] = s;
    __syncthreads();
    for (int off = 1; off < 1024; off <<= 1) {
        int v = (t >= off) ? sums[t - off] : 0;
        __syncthreads();
        sums[t] += v;
        __syncthreads();
    }
    int prev = (t > 0) ? sums[t - 1] : 0;
#pragma unroll
    for (int i = 0; i < 12; i++) {
        if (i >= C) break;
        int idx = base + i;
        if (idx < n) g_rowptr[idx] = local[i] + prev;
    }
}

__global__ void scatter_kernel(const int* __restrict__ src, const int* __restrict__ dst,
                               const float* __restrict__ dist, int E) {
    int e = blockIdx.x * blockDim.x + threadIdx.x;
    if (e < E) {
        int p = atomicAdd(&g_cursor[dst[e]], 1);
        g_csr[p] = make_int2(src[e], __float_as_int(dist[e]));
    }
}

// ======================= Fused filter-table build =======================
// bins b0, b0+1: tab[b][f] = (sum_j ssp(ea(b)@w1+b1)[j]*w2[j][f] + b2[f]) * C(b)
__global__ void __launch_bounds__(128) table_fused(
    const float* __restrict__ w1, const float* __restrict__ b1,
    const float* __restrict__ w2, const float* __restrict__ b2)
{
    __shared__ float a_s[2][H];
    __shared__ float eas[2][G];
    int f = threadIdx.x;
    int b0 = blockIdx.x * 2;
    const float spacing = CUTOFF_F / (G - 1);
    const float coeff = -0.5f / (spacing * spacing);
    if (f < 2 * G) {
        int i = f / G, g = f - i * G;
        float d = (b0 + i) * (CUTOFF_F / NBINS);
        float dd = d - g * spacing;
        eas[i][g] = expf(coeff * dd * dd);
    }
    __syncthreads();
    float bv = b1[f];
    float a0 = bv, a1 = bv;
#pragma unroll
    for (int g = 0; g < G; g++) {
        float w = w1[g * H + f];
        a0 += eas[0][g] * w;
        a1 += eas[1][g] * w;
    }
    a_s[0][f] = sspf(a0);
    a_s[1][f] = sspf(a1);
    __syncthreads();
    unsigned long long accA = 0ull, accB = 0ull;
#pragma unroll 8
    for (int j = 0; j < H; j += 2) {
        float wA = w2[j * H + f];
        float wB = w2[(j + 1) * H + f];
        fma2(accA, pack2(a_s[0][j], a_s[1][j]), bcast2(wA));
        fma2(accB, pack2(a_s[0][j + 1], a_s[1][j + 1]), bcast2(wB));
    }
    float2 vA = unpack2(accA), vB = unpack2(accB);
    float b2v = b2[f];
    float v0 = vA.x + vB.x + b2v;
    float v1 = vA.y + vB.y + b2v;
    if (b0 <= NBINS) {
        float d = b0 * (CUTOFF_F / NBINS);
        g_tabh[b0 * H + f] = __float2half(v0 * 0.5f * (cosf(d * (PI_F / CUTOFF_F)) + 1.f));
    }
    if (b0 + 1 <= NBINS) {
        float d = (b0 + 1) * (CUTOFF_F / NBINS);
        g_tabh[(b0 + 1) * H + f] = __float2half(v1 * 0.5f * (cosf(d * (PI_F / CUTOFF_F)) + 1.f));
    }
}

// ======================= Node GEMM: C[M,128] = epi(A[M,128]@W[128,128]+bias) =======================
#define GF_BIAS   1
#define GF_SSP    2
#define GF_ACC    8
#define GF_HALF   16

template<int FLAGS>
__global__ void __launch_bounds__(128) gemmN(
    const float* __restrict__ A, const float* __restrict__ W,
    const float* __restrict__ bias, float* __restrict__ out, int M)
{
    __shared__ float As[32][36];
    __shared__ float Ws[32][128];
    int tid = threadIdx.x;
    int tx = tid & 15;       // col group: cols tx*8 .. tx*8+7
    int ty = tid >> 4;       // row group: rows ty*4 .. ty*4+3
    int r0 = blockIdx.x * 32;
    unsigned long long acc[4][4];
#pragma unroll
    for (int j = 0; j < 4; j++)
#pragma unroll
        for (int c = 0; c < 4; c++) acc[j][c] = 0ull;

    for (int k0 = 0; k0 < 128; k0 += 32) {
        __syncthreads();
        // A tile: 32 rows x 32 k, as float4 (256 float4 total, 2 per thread)
#pragma unroll
        for (int rep = 0; rep < 2; rep++) {
            int idx = tid + rep * 128;
            int kkg = idx & 7, r = idx >> 3;
            int row = r0 + r;
            float4 v = (row < M) ? *(const float4*)&A[(size_t)row * 128 + k0 + kkg * 4]
                                 : make_float4(0.f, 0.f, 0.f, 0.f);
            *(float4*)&As[r][kkg * 4] = v;
        }
        // W tile: 32 k x 128 cols (1024 float4, 8 per thread)
#pragma unroll
        for (int rep = 0; rep < 8; rep++) {
            int idx = tid + rep * 128;
            int cg = idx & 31, kk = idx >> 5;
            *(float4*)&Ws[kk][cg * 4] = *(const float4*)&W[(size_t)(k0 + kk) * 128 + cg * 4];
        }
        __syncthreads();
#pragma unroll
        for (int kk4 = 0; kk4 < 8; kk4++) {
            float4 av[4];
#pragma unroll
            for (int j = 0; j < 4; j++)
                av[j] = *(const float4*)&As[ty * 4 + j][kk4 * 4];
#pragma unroll
            for (int m = 0; m < 4; m++) {
                ulonglong2 w0 = *(const ulonglong2*)&Ws[kk4 * 4 + m][tx * 8];
                ulonglong2 w1 = *(const ulonglong2*)&Ws[kk4 * 4 + m][tx * 8 + 4];
#pragma unroll
                for (int j = 0; j < 4; j++) {
                    float a = (m == 0) ? av[j].x : (m == 1) ? av[j].y : (m == 2) ? av[j].z : av[j].w;
                    unsigned long long a2 = bcast2(a);
                    fma2(acc[j][0], a2, w0.x);
                    fma2(acc[j][1], a2, w0.y);
                    fma2(acc[j][2], a2, w1.x);
                    fma2(acc[j][3], a2, w1.y);
                }
            }
        }
    }

    float bv[8];
    if (FLAGS & GF_BIAS) {
        float4 bq0 = *(const float4*)&bias[tx * 8];
        float4 bq1 = *(const float4*)&bias[tx * 8 + 4];
        bv[0]=bq0.x; bv[1]=bq0.y; bv[2]=bq0.z; bv[3]=bq0.w;
        bv[4]=bq1.x; bv[5]=bq1.y; bv[6]=bq1.z; bv[7]=bq1.w;
    } else {
#pragma unroll
        for (int i = 0; i < 8; i++) bv[i] = 0.f;
    }
#pragma unroll
    for (int j = 0; j < 4; j++) {
        int row = r0 + ty * 4 + j;
        if (row >= M) continue;
        float v[8];
#pragma unroll
        for (int c = 0; c < 4; c++) {
            float2 p = unpack2(acc[j][c]);
            v[c * 2] = p.x + bv[c * 2];
            v[c * 2 + 1] = p.y + bv[c * 2 + 1];
        }
        if (FLAGS & GF_SSP) {
#pragma unroll
            for (int i = 0; i < 8; i++) v[i] = sspf(v[i]);
        }
        if (FLAGS & GF_HALF) {
            uint4 o;
            o.x = h2_as_u32(__floats2half2_rn(v[0], v[1]));
            o.y = h2_as_u32(__floats2half2_rn(v[2], v[3]));
            o.z = h2_as_u32(__floats2half2_rn(v[4], v[5]));
            o.w = h2_as_u32(__floats2half2_rn(v[6], v[7]));
            *(uint4*)&((__half*)out)[(size_t)row * 128 + tx * 8] = o;
        } else if (FLAGS & GF_ACC) {
            float4* op0 = (float4*)&out[(size_t)row * 128 + tx * 8];
            float4* op1 = op0 + 1;
            float4 o0 = *op0, o1 = *op1;
            o0.x += v[0]; o0.y += v[1]; o0.z += v[2]; o0.w += v[3];
            o1.x += v[4]; o1.y += v[5]; o1.z += v[6]; o1.w += v[7];
            *op0 = o0; *op1 = o1;
        } else {
            *(float4*)&out[(size_t)row * 128 + tx * 8] = make_float4(v[0], v[1], v[2], v[3]);
            *(float4*)&out[(size_t)row * 128 + tx * 8 + 4] = make_float4(v[4], v[5], v[6], v[7]);
        }
    }
}

// ======================= Edge gather (warp per dst node) =======================
__global__ void edge_gather(int N) {
    int warp = (blockIdx.x * blockDim.x + threadIdx.x) >> 5;
    int lane = threadIdx.x & 31;
    if (warp >= N) return;
    int beg = g_rowptr[warp], end = g_rowptr[warp + 1];
    float a0 = 0.f, a1 = 0.f, a2 = 0.f, a3 = 0.f;
#pragma unroll 2
    for (int i = beg; i < end; i++) {
        int2 sd = g_csr[i];
        float d = __int_as_float(sd.y);
        float u = d * ((float)NBINS / CUTOFF_F);
        int i0 = min(max((int)u, 0), NBINS - 1);
        float fr = u - (float)i0;
        uint2 t0 = *(const uint2*)&g_tabh[i0 * H + lane * 4];
        uint2 t1 = *(const uint2*)&g_tabh[(i0 + 1) * H + lane * 4];
        uint2 xq = *(const uint2*)&g_xfh[(size_t)sd.x * H + lane * 4];
        float2 w0a = __half22float2(*(__half2*)&t0.x);
        float2 w0b = __half22float2(*(__half2*)&t0.y);
        float2 w1a = __half22float2(*(__half2*)&t1.x);
        float2 w1b = __half22float2(*(__half2*)&t1.y);
        float2 xa  = __half22float2(*(__half2*)&xq.x);
        float2 xb  = __half22float2(*(__half2*)&xq.y);
        a0 += xa.x * fmaf(fr, w1a.x - w0a.x, w0a.x);
        a1 += xa.y * fmaf(fr, w1a.y - w0a.y, w0a.y);
        a2 += xb.x * fmaf(fr, w1b.x - w0b.x, w0b.x);
        a3 += xb.y * fmaf(fr, w1b.y - w0b.y, w0b.y);
    }
    *(float4*)&g_agg[(size_t)warp * H + lane * 4] = make_float4(a0, a1, a2, a3);
}

// ======================= Readout =======================
// colsum of ssp(h @ o1w + o1b) into g_acc  (64 cols)
__global__ void __launch_bounds__(256) readout_gemm(
    const float* __restrict__ A, const float* __restrict__ W,
    const float* __restrict__ bias, int M)
{
    constexpr int NCOL = 64;
    constexpr int CT = NCOL / 4;   // 16
    constexpr int ROWS = (256 / CT) * 4;  // 64
    __shared__ float As[ROWS][33];
    __shared__ float Ws[32][NCOL];
    __shared__ float csum[NCOL];
    int tid = threadIdx.x;
    int tx = tid % CT, ty = tid / CT;
    int r0 = blockIdx.x * ROWS;
    if (tid < NCOL) csum[tid] = 0.f;
    unsigned long long a01[4] = {0,0,0,0}, a23[4] = {0,0,0,0};
    for (int k0 = 0; k0 < 128; k0 += 32) {
        __syncthreads();
        for (int i = tid; i < ROWS * 32; i += 256) {
            int r = i >> 5, kk = i & 31;
            int row = r0 + r;
            As[r][kk] = (row < M) ? A[(size_t)row * 128 + k0 + kk] : 0.f;
        }
        for (int i = tid; i < 32 * NCOL; i += 256) {
            int kk = i / NCOL, c = i % NCOL;
            Ws[kk][c] = W[(size_t)(k0 + kk) * NCOL + c];
        }
        __syncthreads();
#pragma unroll
        for (int kk = 0; kk < 32; kk++) {
            ulonglong2 wv = *(const ulonglong2*)&Ws[kk][tx * 4];
#pragma unroll
            for (int i = 0; i < 4; i++) {
                unsigned long long a2 = bcast2(As[ty * 4 + i][kk]);
                fma2(a01[i], a2, wv.x);
                fma2(a23[i], a2, wv.y);
            }
        }
    }
    float4 bvq = *(const float4*)&bias[tx * 4];
#pragma unroll
    for (int i = 0; i < 4; i++) {
        int row = r0 + ty * 4 + i;
        if (row >= M) break;
        float2 p0 = unpack2(a01[i]);
        float2 p1 = unpack2(a23[i]);
        atomicAdd(&csum[tx * 4 + 0], sspf(p0.x + bvq.x));
        atomicAdd(&csum[tx * 4 + 1], sspf(p0.y + bvq.y));
        atomicAdd(&csum[tx * 4 + 2], sspf(p1.x + bvq.z));
        atomicAdd(&csum[tx * 4 + 3], sspf(p1.y + bvq.w));
    }
    __syncthreads();
    if (tid < NCOL) atomicAdd(&g_acc[tid], csum[tid]);
}

__global__ void readout_final(const float* __restrict__ o2w, const float* __restrict__ o2b,
                              const float* __restrict__ rw, const float* __restrict__ rb,
                              float* __restrict__ out, int N) {
    __shared__ float v[64];
    int t = threadIdx.x;  // 64
    float a = (float)N * o2b[t];
#pragma unroll 8
    for (int j = 0; j < 64; j++) a += g_acc[j] * o2w[j * 64 + t];
    v[t] = a;
    __syncthreads();
    if (t < 12) {
        float r = rb[t];
#pragma unroll
        for (int j = 0; j < 64; j++) r += v[j] * rw[j * 12 + t];
        out[t] = r;
    }
}

extern "C" void kernel_launch(void* const* d_in, const int* in_sizes, int n_in,
                              void* d_out, int out_size) {
    const int*   x    = (const int*)d_in[0];
    const int*   ei   = (const int*)d_in[1];
    const float* dist = (const float*)d_in[2];
    const float* emb  = (const float*)d_in[3];
    const float* mw1  = (const float*)d_in[4];
    const float* mb1  = (const float*)d_in[5];
    const float* mw2  = (const float*)d_in[6];
    const float* mb2  = (const float*)d_in[7];
    const float* l1w  = (const float*)d_in[8];
    const float* l2w  = (const float*)d_in[9];
    const float* l2b  = (const float*)d_in[10];
    const float* lw   = (const float*)d_in[11];
    const float* lb   = (const float*)d_in[12];
    const float* o1w  = (const float*)d_in[13];
    const float* o1b  = (const float*)d_in[14];
    const float* o2w  = (const float*)d_in[15];
    const float* o2b  = (const float*)d_in[16];
    const float* rw   = (const float*)d_in[17];
    const float* rb   = (const float*)d_in[18];

    int N = in_sizes[0];
    int E = in_sizes[2];
    int L = in_sizes[4] / (G * H);

    float *ph, *pxfh, *pagg, *ptmp, *pacc;
    int *prow, *pcur;
    cudaGetSymbolAddress((void**)&ph, g_h);
    cudaGetSymbolAddress((void**)&pxfh, g_xfh);
    cudaGetSymbolAddress((void**)&pagg, g_agg);
    cudaGetSymbolAddress((void**)&ptmp, g_tmp);
    cudaGetSymbolAddress((void**)&pacc, g_acc);
    cudaGetSymbolAddress((void**)&prow, g_rowptr);
    cudaGetSymbolAddress((void**)&pcur, g_cursor);

    const int* esrc = ei;
    const int* edst = ei + E;

    embed_kernel<<<N, 128>>>(x, emb, N);

    // ---- CSR build (once) ----
    cudaMemsetAsync(prow, 0, (N + 1) * sizeof(int));
    hist_kernel<<<(E + 255) / 256, 256>>>(edst, E);
    scan_kernel<<<1, 1024>>>(N + 1);
    cudaMemcpyAsync(pcur, prow, N * sizeof(int), cudaMemcpyDeviceToDevice);
    scatter_kernel<<<(E + 255) / 256, 256>>>(esrc, edst, dist, E);

    int nbN = (N + 31) / 32;               // gemmN blocks
    int nbE = (N + 7) / 8;                 // edge_gather blocks (8 warps each)
    int nbT = (NBINS + 2) / 2;             // table blocks

    for (int l = 0; l < L; l++) {
        table_fused<<<nbT, 128>>>(mw1 + (size_t)l * G * H, mb1 + (size_t)l * H,
                                  mw2 + (size_t)l * H * H, mb2 + (size_t)l * H);
        gemmN<GF_HALF><<<nbN, 128>>>(ph, l1w + (size_t)l * H * H, nullptr, (float*)pxfh, N);
        edge_gather<<<nbE, 256>>>(N);
        gemmN<GF_BIAS | GF_SSP><<<nbN, 128>>>(pagg, l2w + (size_t)l * H * H,
                                              l2b + (size_t)l * H, ptmp, N);
        gemmN<GF_BIAS | GF_ACC><<<nbN, 128>>>(ptmp, lw + (size_t)l * H * H,
                                              lb + (size_t)l * H, ph, N);
    }

    cudaMemsetAsync(pacc, 0, 64 * sizeof(float));
    readout_gemm<<<(N + 63) / 64, 256>>>(ph, o1w, o1b, N);
    readout_final<<<1, 64>>>(o2w, o2b, rw, rb, (float*)d_out, N);
}